// round 2
// baseline (speedup 1.0000x reference)
#include <cuda_runtime.h>

#define BSZ 2
#define SEQL 2048
#define EMB 1024
#define NH 16
#define HD 64
#define MROWS (BSZ * SEQL)

// Scratch buffers (allocation-free rule -> __device__ globals). 16 MB each.
__device__ float g_q[BSZ * NH * SEQL * HD];    // [b,h,s,d]
__device__ float g_kt[BSZ * NH * HD * SEQL];   // [b,h,d,s]  (K transposed)
__device__ float g_v[BSZ * NH * SEQL * HD];    // [b,h,s,d]
__device__ float g_attn[MROWS * EMB];          // [b*s, e] row-major

// ---------------------------------------------------------------------------
// GEMM: C = A[M,E] @ W[N,E]^T   (y = x @ W^T, torch Linear convention)
// 64x64 tile, BK=16, 256 threads, 4x4 microtile per thread.
// MODE 0: C row-major [M, N]        (output projection)
// MODE 1: C scattered to [b,h,s,d]  (Q, V)
// MODE 2: C scattered to [b,h,d,s]  (K transposed)
// ---------------------------------------------------------------------------
template <int MODE>
__global__ __launch_bounds__(256) void gemm64(const float* __restrict__ A,
                                              const float* __restrict__ W,
                                              float* __restrict__ C) {
    __shared__ float As[16][64];  // [k][m] transposed
    __shared__ float Bs[16][64];  // [k][n] transposed

    const int tid = threadIdx.x;
    const int tx = tid & 15;
    const int ty = tid >> 4;
    const int m0 = blockIdx.y << 6;
    const int n0 = blockIdx.x << 6;

    const int lrow = tid >> 2;         // 0..63
    const int lvec = (tid & 3) << 2;   // 0,4,8,12

    const float* Ap = A + (m0 + lrow) * EMB + lvec;
    const float* Wp = W + (n0 + lrow) * EMB + lvec;

    float acc[4][4];
#pragma unroll
    for (int i = 0; i < 4; i++)
#pragma unroll
        for (int j = 0; j < 4; j++) acc[i][j] = 0.0f;

    for (int kt = 0; kt < EMB; kt += 16) {
        float4 av = *(const float4*)(Ap + kt);
        float4 wv = *(const float4*)(Wp + kt);
        As[lvec + 0][lrow] = av.x;
        As[lvec + 1][lrow] = av.y;
        As[lvec + 2][lrow] = av.z;
        As[lvec + 3][lrow] = av.w;
        Bs[lvec + 0][lrow] = wv.x;
        Bs[lvec + 1][lrow] = wv.y;
        Bs[lvec + 2][lrow] = wv.z;
        Bs[lvec + 3][lrow] = wv.w;
        __syncthreads();

#pragma unroll
        for (int kk = 0; kk < 16; kk++) {
            float4 a4 = *(const float4*)&As[kk][ty << 2];
            float4 b4 = *(const float4*)&Bs[kk][tx << 2];
            float a[4] = {a4.x, a4.y, a4.z, a4.w};
            float b[4] = {b4.x, b4.y, b4.z, b4.w};
#pragma unroll
            for (int i = 0; i < 4; i++)
#pragma unroll
                for (int j = 0; j < 4; j++) acc[i][j] += a[i] * b[j];
        }
        __syncthreads();
    }

    // Epilogue
    if (MODE == 0) {
#pragma unroll
        for (int i = 0; i < 4; i++) {
            int row = m0 + (ty << 2) + i;
            float4 v = {acc[i][0], acc[i][1], acc[i][2], acc[i][3]};
            *(float4*)&C[row * EMB + n0 + (tx << 2)] = v;
        }
    } else if (MODE == 1) {
        const int h = n0 >> 6;  // each 64-wide N tile is exactly one head
#pragma unroll
        for (int i = 0; i < 4; i++) {
            int row = m0 + (ty << 2) + i;
            int b = row >> 11;           // / SEQL
            int s = row & (SEQL - 1);
            float4 v = {acc[i][0], acc[i][1], acc[i][2], acc[i][3]};
            *(float4*)&C[(((b * NH + h) * SEQL + s) << 6) + (tx << 2)] = v;
        }
    } else {  // MODE 2: K transposed [b,h,d,s]
        const int h = n0 >> 6;
#pragma unroll
        for (int i = 0; i < 4; i++) {
            int row = m0 + (ty << 2) + i;
            int b = row >> 11;
            int s = row & (SEQL - 1);
#pragma unroll
            for (int j = 0; j < 4; j++) {
                int d = (tx << 2) + j;
                C[(((b * NH + h) << 6) + d) * SEQL + s] = acc[i][j];
            }
        }
    }
}

// ---------------------------------------------------------------------------
// Causal flash attention, fp32.
// Grid: (qtile 0..31, bh 0..31). Block 256 threads, 64x64 tiles.
// Q loaded transposed [d][s] in smem; K already [d][s] in global.
// KPs smem buffer is reused: K tile during S=QK^T, then P tile for PV.
// NOTE: tiles are 64x64 = 4096 floats; with 256 threads each thread loads
// FOUR float4s (c0 loop). (Round-1 bug: only 1/4 of each tile was loaded.)
// ---------------------------------------------------------------------------
__global__ __launch_bounds__(256) void attn64(const float* __restrict__ Q,
                                              const float* __restrict__ Kt,
                                              const float* __restrict__ V,
                                              float* __restrict__ Out) {
    __shared__ float Qts[64][64];  // [d][row]
    __shared__ float KPs[64][64];  // K: [d][col] -> reused as P: [row][col]
    __shared__ float Vs[64][64];   // [col(k-pos)][d]

    const int tid = threadIdx.x;
    const int tx = tid & 15;
    const int ty = tid >> 4;
    const int qt = blockIdx.x;
    const int bh = blockIdx.y;

    const float* Qb = Q + bh * SEQL * HD;
    const float* Ktb = Kt + bh * HD * SEQL;
    const float* Vb = V + bh * SEQL * HD;

    const int lrow = tid >> 2;         // 0..63
    const int lvec = (tid & 3) << 2;   // 0,4,8,12

    // load Q tile transposed: Qts[d][row]
#pragma unroll
    for (int c0 = 0; c0 < 64; c0 += 16) {
        float4 qv = *(const float4*)&Qb[(qt * 64 + lrow) * HD + c0 + lvec];
        Qts[c0 + lvec + 0][lrow] = qv.x;
        Qts[c0 + lvec + 1][lrow] = qv.y;
        Qts[c0 + lvec + 2][lrow] = qv.z;
        Qts[c0 + lvec + 3][lrow] = qv.w;
    }

    float m_i[4], l_i[4], o[4][4];
#pragma unroll
    for (int i = 0; i < 4; i++) {
        m_i[i] = -1e30f;
        l_i[i] = 0.0f;
#pragma unroll
        for (int j = 0; j < 4; j++) o[i][j] = 0.0f;
    }
    __syncthreads();

    for (int kt2 = 0; kt2 <= qt; kt2++) {
        // K tile: KPs[d=lrow][col], V tile: Vs[k-pos=lrow][d]
#pragma unroll
        for (int c0 = 0; c0 < 64; c0 += 16) {
            *(float4*)&KPs[lrow][c0 + lvec] =
                *(const float4*)&Ktb[lrow * SEQL + kt2 * 64 + c0 + lvec];
            *(float4*)&Vs[lrow][c0 + lvec] =
                *(const float4*)&Vb[(kt2 * 64 + lrow) * HD + c0 + lvec];
        }
        __syncthreads();

        // S = Q K^T
        float sc[4][4];
#pragma unroll
        for (int i = 0; i < 4; i++)
#pragma unroll
            for (int j = 0; j < 4; j++) sc[i][j] = 0.0f;

#pragma unroll 8
        for (int dd = 0; dd < 64; dd++) {
            float4 a4 = *(const float4*)&Qts[dd][ty << 2];
            float4 b4 = *(const float4*)&KPs[dd][tx << 2];
            float a[4] = {a4.x, a4.y, a4.z, a4.w};
            float b[4] = {b4.x, b4.y, b4.z, b4.w};
#pragma unroll
            for (int i = 0; i < 4; i++)
#pragma unroll
                for (int j = 0; j < 4; j++) sc[i][j] += a[i] * b[j];
        }
        __syncthreads();  // all done reading K tile before P overwrites it

        const bool diag = (kt2 == qt);
#pragma unroll
        for (int i = 0; i < 4; i++) {
            const int rloc = (ty << 2) + i;
            float sv[4];
#pragma unroll
            for (int j = 0; j < 4; j++) {
                float v = sc[i][j] * 0.125f;  // 1/sqrt(64)
                if (diag && ((tx << 2) + j) > rloc) v = -1e30f;
                sv[j] = v;
            }
            float rm = fmaxf(fmaxf(sv[0], sv[1]), fmaxf(sv[2], sv[3]));
#pragma unroll
            for (int off = 8; off >= 1; off >>= 1)
                rm = fmaxf(rm, __shfl_xor_sync(0xffffffffu, rm, off));

            float mn = fmaxf(m_i[i], rm);
            float corr = __expf(m_i[i] - mn);
            float p[4];
            float rs = 0.0f;
#pragma unroll
            for (int j = 0; j < 4; j++) {
                p[j] = __expf(sv[j] - mn);
                rs += p[j];
            }
#pragma unroll
            for (int off = 8; off >= 1; off >>= 1)
                rs += __shfl_xor_sync(0xffffffffu, rs, off);

            l_i[i] = l_i[i] * corr + rs;
            m_i[i] = mn;
#pragma unroll
            for (int j = 0; j < 4; j++) o[i][j] *= corr;
#pragma unroll
            for (int j = 0; j < 4; j++) KPs[rloc][(tx << 2) + j] = p[j];
        }
        __syncthreads();

        // O += P @ V
#pragma unroll 8
        for (int j = 0; j < 64; j++) {
            float4 v4 = *(const float4*)&Vs[j][tx << 2];
            float p0 = KPs[(ty << 2) + 0][j];
            float p1 = KPs[(ty << 2) + 1][j];
            float p2 = KPs[(ty << 2) + 2][j];
            float p3 = KPs[(ty << 2) + 3][j];
            o[0][0] += p0 * v4.x; o[0][1] += p0 * v4.y; o[0][2] += p0 * v4.z; o[0][3] += p0 * v4.w;
            o[1][0] += p1 * v4.x; o[1][1] += p1 * v4.y; o[1][2] += p1 * v4.z; o[1][3] += p1 * v4.w;
            o[2][0] += p2 * v4.x; o[2][1] += p2 * v4.y; o[2][2] += p2 * v4.z; o[2][3] += p2 * v4.w;
            o[3][0] += p3 * v4.x; o[3][1] += p3 * v4.y; o[3][2] += p3 * v4.z; o[3][3] += p3 * v4.w;
        }
        __syncthreads();
    }

    // Epilogue: normalize and write to [b*s, e] row-major attn buffer
    const int b = bh >> 4;
    const int h = bh & 15;
#pragma unroll
    for (int i = 0; i < 4; i++) {
        int s = qt * 64 + (ty << 2) + i;
        float inv = 1.0f / l_i[i];
        float4 ov = {o[i][0] * inv, o[i][1] * inv, o[i][2] * inv, o[i][3] * inv};
        *(float4*)&Out[(b * SEQL + s) * EMB + (h << 6) + (tx << 2)] = ov;
    }
}

extern "C" void kernel_launch(void* const* d_in, const int* in_sizes, int n_in,
                              void* d_out, int out_size) {
    const float* x = (const float*)d_in[0];
    const float* w_q = (const float*)d_in[1];
    const float* w_k = (const float*)d_in[2];
    const float* w_v = (const float*)d_in[3];
    const float* w_o = (const float*)d_in[4];
    float* out = (float*)d_out;

    float* q;
    float* kt;
    float* v;
    float* attn;
    cudaGetSymbolAddress((void**)&q, g_q);
    cudaGetSymbolAddress((void**)&kt, g_kt);
    cudaGetSymbolAddress((void**)&v, g_v);
    cudaGetSymbolAddress((void**)&attn, g_attn);

    dim3 ggrid(EMB / 64, MROWS / 64);  // (16, 64)
    gemm64<1><<<ggrid, 256>>>(x, w_q, q);
    gemm64<2><<<ggrid, 256>>>(x, w_k, kt);
    gemm64<1><<<ggrid, 256>>>(x, w_v, v);

    dim3 agrid(SEQL / 64, BSZ * NH);  // (32, 32)
    attn64<<<agrid, 256>>>(q, kt, v, attn);

    gemm64<0><<<ggrid, 256>>>(attn, w_o, out);
}

// round 4
// speedup vs baseline: 1.6587x; 1.6587x over previous
#include <cuda_runtime.h>
#include <cuda_bf16.h>
#include <cstdint>

#define BSZ 2
#define SEQL 2048
#define EMB 1024
#define NH 16
#define HD 64
#define MROWS (BSZ * SEQL)

// ---------------- scratch (__device__ globals; no allocs allowed) ----------
__device__ float g_q[BSZ * NH * SEQL * HD];    // [b,h,s,d]
__device__ float g_kt[BSZ * NH * HD * SEQL];   // [b,h,d,s]
__device__ float g_v[BSZ * NH * SEQL * HD];    // [b,h,s,d]
__device__ float g_attn[MROWS * EMB];          // [b*s, e]

__device__ __nv_bfloat16 g_xhi[MROWS * EMB], g_xlo[MROWS * EMB];
__device__ __nv_bfloat16 g_ahi[MROWS * EMB], g_alo[MROWS * EMB];
__device__ __nv_bfloat16 g_wqhi[EMB * EMB], g_wqlo[EMB * EMB];
__device__ __nv_bfloat16 g_wkhi[EMB * EMB], g_wklo[EMB * EMB];
__device__ __nv_bfloat16 g_wvhi[EMB * EMB], g_wvlo[EMB * EMB];
__device__ __nv_bfloat16 g_wohi[EMB * EMB], g_wolo[EMB * EMB];

// ---------------- PTX helpers (family-compatible only: sm_80-era) -----------
__device__ __forceinline__ uint32_t s2u(const void* p) {
    uint32_t a;
    asm("{ .reg .u64 t; cvta.to.shared.u64 t, %1; cvt.u32.u64 %0, t; }"
        : "=r"(a) : "l"(p));
    return a;
}
__device__ __forceinline__ void cpa16(uint32_t d, const void* g) {
    asm volatile("cp.async.cg.shared.global [%0], [%1], 16;" :: "r"(d), "l"(g));
}
#define CP_COMMIT() asm volatile("cp.async.commit_group;" ::: "memory")
#define CP_WAIT(n) asm volatile("cp.async.wait_group %0;" :: "n"(n) : "memory")

__device__ __forceinline__ void ldsm4(uint32_t* r, uint32_t a) {
    asm volatile("ldmatrix.sync.aligned.m8n8.x4.shared.b16 {%0,%1,%2,%3}, [%4];"
                 : "=r"(r[0]), "=r"(r[1]), "=r"(r[2]), "=r"(r[3]) : "r"(a));
}
__device__ __forceinline__ void ldsm2(uint32_t* r, uint32_t a) {
    asm volatile("ldmatrix.sync.aligned.m8n8.x2.shared.b16 {%0,%1}, [%2];"
                 : "=r"(r[0]), "=r"(r[1]) : "r"(a));
}
__device__ __forceinline__ void mma16816(float* c, const uint32_t* a, const uint32_t* b) {
    asm volatile(
        "mma.sync.aligned.m16n8k16.row.col.f32.bf16.bf16.f32 "
        "{%0,%1,%2,%3}, {%4,%5,%6,%7}, {%8,%9}, {%0,%1,%2,%3};"
        : "+f"(c[0]), "+f"(c[1]), "+f"(c[2]), "+f"(c[3])
        : "r"(a[0]), "r"(a[1]), "r"(a[2]), "r"(a[3]), "r"(b[0]), "r"(b[1]));
}

// ---------------- fp32 -> bf16 hi/lo split ----------------------------------
__global__ __launch_bounds__(256) void cvt_split(const float* __restrict__ in,
                                                 __nv_bfloat16* __restrict__ hi,
                                                 __nv_bfloat16* __restrict__ lo,
                                                 int n4) {
    int i = blockIdx.x * 256 + threadIdx.x;
    if (i >= n4) return;
    float4 v = ((const float4*)in)[i];
    __nv_bfloat16 h0 = __float2bfloat16(v.x);
    __nv_bfloat16 h1 = __float2bfloat16(v.y);
    __nv_bfloat16 h2 = __float2bfloat16(v.z);
    __nv_bfloat16 h3 = __float2bfloat16(v.w);
    __nv_bfloat16 l0 = __float2bfloat16(v.x - __bfloat162float(h0));
    __nv_bfloat16 l1 = __float2bfloat16(v.y - __bfloat162float(h1));
    __nv_bfloat16 l2 = __float2bfloat16(v.z - __bfloat162float(h2));
    __nv_bfloat16 l3 = __float2bfloat16(v.w - __bfloat162float(h3));
    __nv_bfloat162* hp = (__nv_bfloat162*)hi;
    __nv_bfloat162* lp = (__nv_bfloat162*)lo;
    hp[2 * i] = __nv_bfloat162(h0, h1);
    hp[2 * i + 1] = __nv_bfloat162(h2, h3);
    lp[2 * i] = __nv_bfloat162(l0, l1);
    lp[2 * i + 1] = __nv_bfloat162(l2, l3);
}

// ---------------- mma.sync bf16x3 GEMM: C = A @ B^T -------------------------
// A[4096,1024] K-major, B[1024,1024] K-major (torch Linear weight), C fp32.
// CTA tile 128x128, BK=32, 3-stage cp.async. 8 warps: 4(m) x 2(n),
// warp tile 32(m) x 64(n) = 2 x 8 fragments of m16n8k16.
// MODE 0: C row-major; MODE 1: scatter [b,h,s,d]; MODE 2: scatter [b,h,d,s].
#define TM 128
#define TN 128
#define KB 32
#define NCH (EMB / KB)       // 32
#define ROWB 80              // padded row stride in bytes (40 bf16)
#define MAT_B (128 * ROWB)   // 10240
#define OFF_AH 0
#define OFF_AL MAT_B
#define OFF_BH (2 * MAT_B)
#define OFF_BL (3 * MAT_B)
#define STAGE_B (4 * MAT_B)  // 40960
#define SM_TOTAL (3 * STAGE_B)

template <int MODE>
__global__ __launch_bounds__(256, 1)
void gemm_mma(const __nv_bfloat16* __restrict__ Ahi, const __nv_bfloat16* __restrict__ Alo,
              const __nv_bfloat16* __restrict__ Bhi, const __nv_bfloat16* __restrict__ Blo,
              float* __restrict__ C) {
    extern __shared__ __align__(128) char smem[];
    const uint32_t sb = s2u(smem);
    const int tid = threadIdx.x;
    const int wid = tid >> 5;
    const int lane = tid & 31;
    const int m0 = blockIdx.y * TM;
    const int n0 = blockIdx.x * TN;
    const int wm0 = (wid >> 1) * 32;   // warp m-offset in tile
    const int wn0 = (wid & 1) * 64;    // warp n-offset in tile

    // gmem load geometry: each thread covers 2 x 16B per matrix per chunk
    // chunk element id = tid + 256*i -> row = id>>2 (0..127), c4 = id&3
    const int lr0 = tid >> 2;          // row for i=0
    const int lc0 = tid & 3;           // 16B-col
    const __nv_bfloat16* pAh = Ahi + (size_t)(m0 + lr0) * EMB + lc0 * 8;
    const __nv_bfloat16* pAl = Alo + (size_t)(m0 + lr0) * EMB + lc0 * 8;
    const __nv_bfloat16* pBh = Bhi + (size_t)(n0 + lr0) * EMB + lc0 * 8;
    const __nv_bfloat16* pBl = Blo + (size_t)(n0 + lr0) * EMB + lc0 * 8;
    const uint32_t so0 = lr0 * ROWB + lc0 * 16;

    auto load_chunk = [&](int c, int s) {
        const uint32_t base = sb + s * STAGE_B;
        const int kb = c * KB;
#pragma unroll
        for (int i = 0; i < 2; i++) {
            const uint32_t so = so0 + i * 64 * ROWB;       // +64 rows
            const size_t go = (size_t)(64 * i) * EMB + kb;
            cpa16(base + OFF_AH + so, pAh + go);
            cpa16(base + OFF_AL + so, pAl + go);
            cpa16(base + OFF_BH + so, pBh + go);
            cpa16(base + OFF_BL + so, pBl + go);
        }
        CP_COMMIT();
    };

    float acc[2][8][4];
#pragma unroll
    for (int mf = 0; mf < 2; mf++)
#pragma unroll
        for (int nf = 0; nf < 8; nf++)
#pragma unroll
            for (int j = 0; j < 4; j++) acc[mf][nf][j] = 0.0f;

    // ldmatrix per-lane addresses (offsets within a stage)
    // A x4: rows wm0+mf*16+(lane&15), +16B half for lanes>=16
    const uint32_t aRow = wm0 + (lane & 15);
    const uint32_t aHalf = (lane >> 4) * 16;
    // B x2: rows wn0+nf*8+(lane&7), +16B half for (lane>>3)&1 (lanes 0-15 used)
    const uint32_t bRow = wn0 + (lane & 7);
    const uint32_t bHalf = ((lane >> 3) & 1) * 16;

    load_chunk(0, 0);
    load_chunk(1, 1);

    for (int c = 0; c < NCH; c++) {
        const int s = c - (c / 3) * 3;  // c % 3
        if (c + 2 < NCH) { CP_WAIT(1); } else { CP_WAIT(0); }
        __syncthreads();
        if (c + 2 < NCH) load_chunk(c + 2, s == 0 ? 2 : s - 1);  // (c+2)%3

        const uint32_t st = sb + s * STAGE_B;
#pragma unroll
        for (int kk = 0; kk < 2; kk++) {
            uint32_t ah[2][4], al[2][4];
#pragma unroll
            for (int mf = 0; mf < 2; mf++) {
                const uint32_t ao = (aRow + mf * 16) * ROWB + kk * 32 + aHalf;
                ldsm4(ah[mf], st + OFF_AH + ao);
                ldsm4(al[mf], st + OFF_AL + ao);
            }
#pragma unroll
            for (int nf = 0; nf < 8; nf++) {
                uint32_t bh[2], bl[2];
                const uint32_t bo = (bRow + nf * 8) * ROWB + kk * 32 + bHalf;
                ldsm2(bh, st + OFF_BH + bo);
                ldsm2(bl, st + OFF_BL + bo);
#pragma unroll
                for (int mf = 0; mf < 2; mf++) {
                    mma16816(acc[mf][nf], ah[mf], bh);
                    mma16816(acc[mf][nf], ah[mf], bl);
                    mma16816(acc[mf][nf], al[mf], bh);
                }
            }
        }
    }

    // epilogue: thread holds (m = mrow, mrow+8; n = ncol, ncol+1) per fragment
#pragma unroll
    for (int mf = 0; mf < 2; mf++) {
        const int mrow = m0 + wm0 + mf * 16 + (lane >> 2);
#pragma unroll
        for (int half = 0; half < 2; half++) {
            const int row = mrow + half * 8;
            const int b = row >> 11;
            const int sdx = row & (SEQL - 1);
#pragma unroll
            for (int nf = 0; nf < 8; nf++) {
                const int col = n0 + wn0 + nf * 8 + 2 * (lane & 3);
                const float c0 = acc[mf][nf][2 * half];
                const float c1 = acc[mf][nf][2 * half + 1];
                if (MODE == 0) {
                    float2 v = {c0, c1};
                    *(float2*)&C[(size_t)row * EMB + col] = v;
                } else if (MODE == 1) {
                    const int h = col >> 6;
                    const int d = col & 63;
                    float2 v = {c0, c1};
                    *(float2*)&C[(((size_t)(b * NH + h) * SEQL + sdx) << 6) + d] = v;
                } else {
                    const int h = col >> 6;
                    const int d = col & 63;
                    C[(size_t)((b * NH + h) * HD + d) * SEQL + sdx] = c0;
                    C[(size_t)((b * NH + h) * HD + d + 1) * SEQL + sdx] = c1;
                }
            }
        }
    }
}

// ---------------- causal flash attention, fp32 (unchanged, known-good) ------
__global__ __launch_bounds__(256) void attn64(const float* __restrict__ Q,
                                              const float* __restrict__ Kt,
                                              const float* __restrict__ V,
                                              float* __restrict__ Out) {
    __shared__ float Qts[64][64];
    __shared__ float KPs[64][64];
    __shared__ float Vs[64][64];

    const int tid = threadIdx.x;
    const int tx = tid & 15;
    const int ty = tid >> 4;
    const int qt = blockIdx.x;
    const int bh = blockIdx.y;

    const float* Qb = Q + bh * SEQL * HD;
    const float* Ktb = Kt + bh * HD * SEQL;
    const float* Vb = V + bh * SEQL * HD;

    const int lrow = tid >> 2;
    const int lvec = (tid & 3) << 2;

#pragma unroll
    for (int c0 = 0; c0 < 64; c0 += 16) {
        float4 qv = *(const float4*)&Qb[(qt * 64 + lrow) * HD + c0 + lvec];
        Qts[c0 + lvec + 0][lrow] = qv.x;
        Qts[c0 + lvec + 1][lrow] = qv.y;
        Qts[c0 + lvec + 2][lrow] = qv.z;
        Qts[c0 + lvec + 3][lrow] = qv.w;
    }

    float m_i[4], l_i[4], o[4][4];
#pragma unroll
    for (int i = 0; i < 4; i++) {
        m_i[i] = -1e30f;
        l_i[i] = 0.0f;
#pragma unroll
        for (int j = 0; j < 4; j++) o[i][j] = 0.0f;
    }
    __syncthreads();

    for (int kt2 = 0; kt2 <= qt; kt2++) {
#pragma unroll
        for (int c0 = 0; c0 < 64; c0 += 16) {
            *(float4*)&KPs[lrow][c0 + lvec] =
                *(const float4*)&Ktb[lrow * SEQL + kt2 * 64 + c0 + lvec];
            *(float4*)&Vs[lrow][c0 + lvec] =
                *(const float4*)&Vb[(kt2 * 64 + lrow) * HD + c0 + lvec];
        }
        __syncthreads();

        float sc[4][4];
#pragma unroll
        for (int i = 0; i < 4; i++)
#pragma unroll
            for (int j = 0; j < 4; j++) sc[i][j] = 0.0f;

#pragma unroll 8
        for (int dd = 0; dd < 64; dd++) {
            float4 a4 = *(const float4*)&Qts[dd][ty << 2];
            float4 b4 = *(const float4*)&KPs[dd][tx << 2];
            float a[4] = {a4.x, a4.y, a4.z, a4.w};
            float b[4] = {b4.x, b4.y, b4.z, b4.w};
#pragma unroll
            for (int i = 0; i < 4; i++)
#pragma unroll
                for (int j = 0; j < 4; j++) sc[i][j] += a[i] * b[j];
        }
        __syncthreads();

        const bool diag = (kt2 == qt);
#pragma unroll
        for (int i = 0; i < 4; i++) {
            const int rloc = (ty << 2) + i;
            float sv[4];
#pragma unroll
            for (int j = 0; j < 4; j++) {
                float v = sc[i][j] * 0.125f;
                if (diag && ((tx << 2) + j) > rloc) v = -1e30f;
                sv[j] = v;
            }
            float rm = fmaxf(fmaxf(sv[0], sv[1]), fmaxf(sv[2], sv[3]));
#pragma unroll
            for (int off = 8; off >= 1; off >>= 1)
                rm = fmaxf(rm, __shfl_xor_sync(0xffffffffu, rm, off));

            float mn = fmaxf(m_i[i], rm);
            float corr = __expf(m_i[i] - mn);
            float p[4];
            float rs = 0.0f;
#pragma unroll
            for (int j = 0; j < 4; j++) {
                p[j] = __expf(sv[j] - mn);
                rs += p[j];
            }
#pragma unroll
            for (int off = 8; off >= 1; off >>= 1)
                rs += __shfl_xor_sync(0xffffffffu, rs, off);

            l_i[i] = l_i[i] * corr + rs;
            m_i[i] = mn;
#pragma unroll
            for (int j = 0; j < 4; j++) o[i][j] *= corr;
#pragma unroll
            for (int j = 0; j < 4; j++) KPs[rloc][(tx << 2) + j] = p[j];
        }
        __syncthreads();

#pragma unroll 8
        for (int j = 0; j < 64; j++) {
            float4 v4 = *(const float4*)&Vs[j][tx << 2];
            float p0 = KPs[(ty << 2) + 0][j];
            float p1 = KPs[(ty << 2) + 1][j];
            float p2 = KPs[(ty << 2) + 2][j];
            float p3 = KPs[(ty << 2) + 3][j];
            o[0][0] += p0 * v4.x; o[0][1] += p0 * v4.y; o[0][2] += p0 * v4.z; o[0][3] += p0 * v4.w;
            o[1][0] += p1 * v4.x; o[1][1] += p1 * v4.y; o[1][2] += p1 * v4.z; o[1][3] += p1 * v4.w;
            o[2][0] += p2 * v4.x; o[2][1] += p2 * v4.y; o[2][2] += p2 * v4.z; o[2][3] += p2 * v4.w;
            o[3][0] += p3 * v4.x; o[3][1] += p3 * v4.y; o[3][2] += p3 * v4.z; o[3][3] += p3 * v4.w;
        }
        __syncthreads();
    }

    const int b = bh >> 4;
    const int h = bh & 15;
#pragma unroll
    for (int i = 0; i < 4; i++) {
        int s = qt * 64 + (ty << 2) + i;
        float inv = 1.0f / l_i[i];
        float4 ov = {o[i][0] * inv, o[i][1] * inv, o[i][2] * inv, o[i][3] * inv};
        *(float4*)&Out[(b * SEQL + s) * EMB + (h << 6) + (tx << 2)] = ov;
    }
}

// ---------------- launch -----------------------------------------------------
extern "C" void kernel_launch(void* const* d_in, const int* in_sizes, int n_in,
                              void* d_out, int out_size) {
    const float* x = (const float*)d_in[0];
    const float* w_q = (const float*)d_in[1];
    const float* w_k = (const float*)d_in[2];
    const float* w_v = (const float*)d_in[3];
    const float* w_o = (const float*)d_in[4];
    float* out = (float*)d_out;

    float *q, *kt, *v, *attn;
    cudaGetSymbolAddress((void**)&q, g_q);
    cudaGetSymbolAddress((void**)&kt, g_kt);
    cudaGetSymbolAddress((void**)&v, g_v);
    cudaGetSymbolAddress((void**)&attn, g_attn);
    __nv_bfloat16 *xhi, *xlo, *ahi, *alo;
    __nv_bfloat16 *wqh, *wql, *wkh, *wkl, *wvh, *wvl, *woh, *wol;
    cudaGetSymbolAddress((void**)&xhi, g_xhi);
    cudaGetSymbolAddress((void**)&xlo, g_xlo);
    cudaGetSymbolAddress((void**)&ahi, g_ahi);
    cudaGetSymbolAddress((void**)&alo, g_alo);
    cudaGetSymbolAddress((void**)&wqh, g_wqhi);
    cudaGetSymbolAddress((void**)&wql, g_wqlo);
    cudaGetSymbolAddress((void**)&wkh, g_wkhi);
    cudaGetSymbolAddress((void**)&wkl, g_wklo);
    cudaGetSymbolAddress((void**)&wvh, g_wvhi);
    cudaGetSymbolAddress((void**)&wvl, g_wvlo);
    cudaGetSymbolAddress((void**)&woh, g_wohi);
    cudaGetSymbolAddress((void**)&wol, g_wolo);

    cudaFuncSetAttribute(gemm_mma<0>, cudaFuncAttributeMaxDynamicSharedMemorySize, SM_TOTAL);
    cudaFuncSetAttribute(gemm_mma<1>, cudaFuncAttributeMaxDynamicSharedMemorySize, SM_TOTAL);
    cudaFuncSetAttribute(gemm_mma<2>, cudaFuncAttributeMaxDynamicSharedMemorySize, SM_TOTAL);

    const int nx4 = MROWS * EMB / 4;   // 1048576
    const int nw4 = EMB * EMB / 4;     // 262144
    cvt_split<<<nx4 / 256, 256>>>(x, xhi, xlo, nx4);
    cvt_split<<<nw4 / 256, 256>>>(w_q, wqh, wql, nw4);
    cvt_split<<<nw4 / 256, 256>>>(w_k, wkh, wkl, nw4);
    cvt_split<<<nw4 / 256, 256>>>(w_v, wvh, wvl, nw4);
    cvt_split<<<nw4 / 256, 256>>>(w_o, woh, wol, nw4);

    dim3 ggrid(EMB / TN, MROWS / TM);  // (8, 32)
    gemm_mma<1><<<ggrid, 256, SM_TOTAL>>>(xhi, xlo, wqh, wql, q);
    gemm_mma<2><<<ggrid, 256, SM_TOTAL>>>(xhi, xlo, wkh, wkl, kt);
    gemm_mma<1><<<ggrid, 256, SM_TOTAL>>>(xhi, xlo, wvh, wvl, v);

    dim3 agrid(SEQL / 64, BSZ * NH);   // (32, 32)
    attn64<<<agrid, 256>>>(q, kt, v, attn);

    cvt_split<<<nx4 / 256, 256>>>(attn, ahi, alo, nx4);
    gemm_mma<0><<<ggrid, 256, SM_TOTAL>>>(ahi, alo, woh, wol, out);
}

// round 5
// speedup vs baseline: 3.0364x; 1.8306x over previous
#include <cuda_runtime.h>
#include <cuda_bf16.h>
#include <cstdint>

#define BSZ 2
#define SEQL 2048
#define EMB 1024
#define NH 16
#define HD 64
#define MROWS (BSZ * SEQL)

// ---------------- scratch (__device__ globals; no allocs allowed) ----------
__device__ __nv_bfloat16 g_xhi[MROWS * EMB], g_xlo[MROWS * EMB];
__device__ __nv_bfloat16 g_ahi[MROWS * EMB], g_alo[MROWS * EMB];
__device__ __nv_bfloat16 g_qhi[BSZ * NH * SEQL * HD], g_qlo[BSZ * NH * SEQL * HD];
__device__ __nv_bfloat16 g_khi[BSZ * NH * SEQL * HD], g_klo[BSZ * NH * SEQL * HD];
__device__ __nv_bfloat16 g_vhi[BSZ * NH * SEQL * HD], g_vlo[BSZ * NH * SEQL * HD];
__device__ __nv_bfloat16 g_wqhi[EMB * EMB], g_wqlo[EMB * EMB];
__device__ __nv_bfloat16 g_wkhi[EMB * EMB], g_wklo[EMB * EMB];
__device__ __nv_bfloat16 g_wvhi[EMB * EMB], g_wvlo[EMB * EMB];
__device__ __nv_bfloat16 g_wohi[EMB * EMB], g_wolo[EMB * EMB];

// ---------------- PTX helpers (family-compatible, sm_80-era) ----------------
__device__ __forceinline__ uint32_t s2u(const void* p) {
    uint32_t a;
    asm("{ .reg .u64 t; cvta.to.shared.u64 t, %1; cvt.u32.u64 %0, t; }"
        : "=r"(a) : "l"(p));
    return a;
}
__device__ __forceinline__ void cpa16(uint32_t d, const void* g) {
    asm volatile("cp.async.cg.shared.global [%0], [%1], 16;" :: "r"(d), "l"(g));
}
#define CP_COMMIT() asm volatile("cp.async.commit_group;" ::: "memory")
#define CP_WAIT(n) asm volatile("cp.async.wait_group %0;" :: "n"(n) : "memory")

__device__ __forceinline__ void ldsm4(uint32_t* r, uint32_t a) {
    asm volatile("ldmatrix.sync.aligned.m8n8.x4.shared.b16 {%0,%1,%2,%3}, [%4];"
                 : "=r"(r[0]), "=r"(r[1]), "=r"(r[2]), "=r"(r[3]) : "r"(a));
}
__device__ __forceinline__ void ldsm2(uint32_t* r, uint32_t a) {
    asm volatile("ldmatrix.sync.aligned.m8n8.x2.shared.b16 {%0,%1}, [%2];"
                 : "=r"(r[0]), "=r"(r[1]) : "r"(a));
}
__device__ __forceinline__ void ldsm2t(uint32_t* r, uint32_t a) {
    asm volatile("ldmatrix.sync.aligned.m8n8.x2.trans.shared.b16 {%0,%1}, [%2];"
                 : "=r"(r[0]), "=r"(r[1]) : "r"(a));
}
__device__ __forceinline__ void mma16816(float* c, const uint32_t* a, const uint32_t* b) {
    asm volatile(
        "mma.sync.aligned.m16n8k16.row.col.f32.bf16.bf16.f32 "
        "{%0,%1,%2,%3}, {%4,%5,%6,%7}, {%8,%9}, {%0,%1,%2,%3};"
        : "+f"(c[0]), "+f"(c[1]), "+f"(c[2]), "+f"(c[3])
        : "r"(a[0]), "r"(a[1]), "r"(a[2]), "r"(a[3]), "r"(b[0]), "r"(b[1]));
}
// split 2 fp32 into packed bf16x2 hi and lo parts
__device__ __forceinline__ void split2(float x, float y, uint32_t& h, uint32_t& l) {
    __nv_bfloat16 hx = __float2bfloat16(x);
    __nv_bfloat16 hy = __float2bfloat16(y);
    __nv_bfloat162 hv(hx, hy);
    __nv_bfloat162 lv(__float2bfloat16(x - __bfloat162float(hx)),
                      __float2bfloat16(y - __bfloat162float(hy)));
    h = *(uint32_t*)&hv;
    l = *(uint32_t*)&lv;
}

// ---------------- fp32 -> bf16 hi/lo split ----------------------------------
__global__ __launch_bounds__(256) void cvt_split(const float* __restrict__ in,
                                                 __nv_bfloat16* __restrict__ hi,
                                                 __nv_bfloat16* __restrict__ lo,
                                                 int n4) {
    int i = blockIdx.x * 256 + threadIdx.x;
    if (i >= n4) return;
    float4 v = ((const float4*)in)[i];
    uint32_t h0, l0, h1, l1;
    split2(v.x, v.y, h0, l0);
    split2(v.z, v.w, h1, l1);
    ((uint32_t*)hi)[2 * i] = h0;
    ((uint32_t*)hi)[2 * i + 1] = h1;
    ((uint32_t*)lo)[2 * i] = l0;
    ((uint32_t*)lo)[2 * i + 1] = l1;
}

// ---------------- mma.sync bf16x3 GEMM: C = A @ B^T -------------------------
// CTA tile 128x128, BK=32, 3-stage cp.async. 8 warps: 4(m) x 2(n).
// MODE 0: fp32 C row-major; MODE 1: bf16 hi/lo scatter to [b,h,s,d]
#define TM 128
#define TN 128
#define KB 32
#define NCH (EMB / KB)
#define ROWB 80
#define MAT_B (128 * ROWB)
#define OFF_AH 0
#define OFF_AL MAT_B
#define OFF_BH (2 * MAT_B)
#define OFF_BL (3 * MAT_B)
#define STAGE_B (4 * MAT_B)
#define SM_TOTAL (3 * STAGE_B)

template <int MODE>
__global__ __launch_bounds__(256, 1)
void gemm_mma(const __nv_bfloat16* __restrict__ Ahi, const __nv_bfloat16* __restrict__ Alo,
              const __nv_bfloat16* __restrict__ Bhi, const __nv_bfloat16* __restrict__ Blo,
              float* __restrict__ C,
              __nv_bfloat16* __restrict__ Chi, __nv_bfloat16* __restrict__ Clo) {
    extern __shared__ __align__(128) char smem[];
    const uint32_t sb = s2u(smem);
    const int tid = threadIdx.x;
    const int wid = tid >> 5;
    const int lane = tid & 31;
    const int m0 = blockIdx.y * TM;
    const int n0 = blockIdx.x * TN;
    const int wm0 = (wid >> 1) * 32;
    const int wn0 = (wid & 1) * 64;

    const int lr0 = tid >> 2;
    const int lc0 = tid & 3;
    const __nv_bfloat16* pAh = Ahi + (size_t)(m0 + lr0) * EMB + lc0 * 8;
    const __nv_bfloat16* pAl = Alo + (size_t)(m0 + lr0) * EMB + lc0 * 8;
    const __nv_bfloat16* pBh = Bhi + (size_t)(n0 + lr0) * EMB + lc0 * 8;
    const __nv_bfloat16* pBl = Blo + (size_t)(n0 + lr0) * EMB + lc0 * 8;
    const uint32_t so0 = lr0 * ROWB + lc0 * 16;

    auto load_chunk = [&](int c, int s) {
        const uint32_t base = sb + s * STAGE_B;
        const int kb = c * KB;
#pragma unroll
        for (int i = 0; i < 2; i++) {
            const uint32_t so = so0 + i * 64 * ROWB;
            const size_t go = (size_t)(64 * i) * EMB + kb;
            cpa16(base + OFF_AH + so, pAh + go);
            cpa16(base + OFF_AL + so, pAl + go);
            cpa16(base + OFF_BH + so, pBh + go);
            cpa16(base + OFF_BL + so, pBl + go);
        }
        CP_COMMIT();
    };

    float acc[2][8][4];
#pragma unroll
    for (int mf = 0; mf < 2; mf++)
#pragma unroll
        for (int nf = 0; nf < 8; nf++)
#pragma unroll
            for (int j = 0; j < 4; j++) acc[mf][nf][j] = 0.0f;

    const uint32_t aRow = wm0 + (lane & 15);
    const uint32_t aHalf = (lane >> 4) * 16;
    const uint32_t bRow = wn0 + (lane & 7);
    const uint32_t bHalf = ((lane >> 3) & 1) * 16;

    load_chunk(0, 0);
    load_chunk(1, 1);

    for (int c = 0; c < NCH; c++) {
        const int s = c - (c / 3) * 3;
        if (c + 2 < NCH) { CP_WAIT(1); } else { CP_WAIT(0); }
        __syncthreads();
        if (c + 2 < NCH) load_chunk(c + 2, s == 0 ? 2 : s - 1);

        const uint32_t st = sb + s * STAGE_B;
#pragma unroll
        for (int kk = 0; kk < 2; kk++) {
            uint32_t ah[2][4], al[2][4];
#pragma unroll
            for (int mf = 0; mf < 2; mf++) {
                const uint32_t ao = (aRow + mf * 16) * ROWB + kk * 32 + aHalf;
                ldsm4(ah[mf], st + OFF_AH + ao);
                ldsm4(al[mf], st + OFF_AL + ao);
            }
#pragma unroll
            for (int nf = 0; nf < 8; nf++) {
                uint32_t bh[2], bl[2];
                const uint32_t bo = (bRow + nf * 8) * ROWB + kk * 32 + bHalf;
                ldsm2(bh, st + OFF_BH + bo);
                ldsm2(bl, st + OFF_BL + bo);
#pragma unroll
                for (int mf = 0; mf < 2; mf++) {
                    mma16816(acc[mf][nf], ah[mf], bh);
                    mma16816(acc[mf][nf], ah[mf], bl);
                    mma16816(acc[mf][nf], al[mf], bh);
                }
            }
        }
    }

#pragma unroll
    for (int mf = 0; mf < 2; mf++) {
        const int mrow = m0 + wm0 + mf * 16 + (lane >> 2);
#pragma unroll
        for (int half = 0; half < 2; half++) {
            const int row = mrow + half * 8;
            const int b = row >> 11;
            const int sdx = row & (SEQL - 1);
#pragma unroll
            for (int nf = 0; nf < 8; nf++) {
                const int col = n0 + wn0 + nf * 8 + 2 * (lane & 3);
                const float c0 = acc[mf][nf][2 * half];
                const float c1 = acc[mf][nf][2 * half + 1];
                if (MODE == 0) {
                    float2 v = {c0, c1};
                    *(float2*)&C[(size_t)row * EMB + col] = v;
                } else {
                    const int h = col >> 6;
                    const int d = col & 63;
                    uint32_t hv, lv;
                    split2(c0, c1, hv, lv);
                    const size_t idx = (((size_t)(b * NH + h) * SEQL + sdx) << 6) + d;
                    *(uint32_t*)&Chi[idx] = hv;
                    *(uint32_t*)&Clo[idx] = lv;
                }
            }
        }
    }
}

// ---------------- tensor-core causal flash attention (bf16x3) ----------------
// CTA: 128 q rows, 8 warps x 16 rows. K chunks of 64. Everything register-local
// after smem K/V tiles. Q/K/V/P all in hi+lo bf16 split (3-term products).
#define QT 128
#define ST 64
#define KROWB 144                    // 64 bf16 cols = 128B data + 16B pad
#define KVTILE (ST * KROWB)          // 9216
#define AT_STAGE (4 * KVTILE)        // 36864: Khi,Klo,Vhi,Vlo
#define AT_SMEM (2 * AT_STAGE)       // 73728

__global__ __launch_bounds__(256, 1)
void attn_mma(const __nv_bfloat16* __restrict__ Qhi, const __nv_bfloat16* __restrict__ Qlo,
              const __nv_bfloat16* __restrict__ Khi, const __nv_bfloat16* __restrict__ Klo,
              const __nv_bfloat16* __restrict__ Vhi, const __nv_bfloat16* __restrict__ Vlo,
              __nv_bfloat16* __restrict__ Ohi, __nv_bfloat16* __restrict__ Olo) {
    extern __shared__ __align__(128) char smem[];
    const uint32_t sb = s2u(smem);
    const int tid = threadIdx.x;
    const int wid = tid >> 5;
    const int lane = tid & 31;
    const int qt = (SEQL / QT - 1) - (blockIdx.x >> 5);  // heavy tiles first
    const int bh = blockIdx.x & 31;
    const size_t hoff = (size_t)bh * SEQL * HD;

    // ---- stage Q tile (hi at sb+0, lo at sb+QSTG), move to registers ----
#define QSTG (QT * KROWB)  // 18432
    {
        const int r = tid >> 1;
        const int cs = (tid & 1) * 4;
        const __nv_bfloat16* qh = Qhi + hoff + (size_t)(qt * QT + r) * HD + cs * 8;
        const __nv_bfloat16* ql = Qlo + hoff + (size_t)(qt * QT + r) * HD + cs * 8;
#pragma unroll
        for (int i = 0; i < 4; i++) {
            cpa16(sb + r * KROWB + (cs + i) * 16, qh + i * 8);
            cpa16(sb + QSTG + r * KROWB + (cs + i) * 16, ql + i * 8);
        }
        CP_COMMIT();
        CP_WAIT(0);
        __syncthreads();
    }
    uint32_t qah[4][4], qal[4][4];
    {
        const uint32_t qa0 = (16 * wid + (lane & 15)) * KROWB + (lane >> 4) * 16;
#pragma unroll
        for (int kk = 0; kk < 4; kk++) {
            ldsm4(qah[kk], sb + qa0 + kk * 32);
            ldsm4(qal[kk], sb + QSTG + qa0 + kk * 32);
        }
    }
    __syncthreads();  // Q staging free before KV loads overwrite it

    auto load_kv = [&](int c, int stg) {
        const uint32_t base = sb + stg * AT_STAGE;
        const size_t g0 = hoff + (size_t)(c * ST) * HD;
#pragma unroll
        for (int i = 0; i < 2; i++) {
            const int id = tid + 256 * i;
            const int r = id >> 3;
            const int sg = id & 7;
            const uint32_t so = r * KROWB + sg * 16;
            const size_t go = g0 + (size_t)r * HD + sg * 8;
            cpa16(base + so, Khi + go);
            cpa16(base + KVTILE + so, Klo + go);
            cpa16(base + 2 * KVTILE + so, Vhi + go);
            cpa16(base + 3 * KVTILE + so, Vlo + go);
        }
        CP_COMMIT();
    };

    float m_[2] = {-1e30f, -1e30f};
    float l_[2] = {0.0f, 0.0f};
    float o[8][4];
#pragma unroll
    for (int nf = 0; nf < 8; nf++)
#pragma unroll
        for (int j = 0; j < 4; j++) o[nf][j] = 0.0f;

    const int nch = 2 * qt + 2;
    load_kv(0, 0);
    if (nch > 1) load_kv(1, 1);

    const int rowa = qt * QT + 16 * wid + (lane >> 2);

    for (int c = 0; c < nch; c++) {
        if (c + 1 < nch) { CP_WAIT(1); } else { CP_WAIT(0); }
        __syncthreads();
        const uint32_t st = sb + (c & 1) * AT_STAGE;

        // ---- S = Q K^T (bf16x3) ----
        float s[8][4];
#pragma unroll
        for (int nf = 0; nf < 8; nf++)
#pragma unroll
            for (int j = 0; j < 4; j++) s[nf][j] = 0.0f;
#pragma unroll
        for (int kk = 0; kk < 4; kk++) {
#pragma unroll
            for (int nf = 0; nf < 8; nf++) {
                uint32_t kh[2], kl[2];
                const uint32_t bo =
                    (nf * 8 + (lane & 7)) * KROWB + kk * 32 + ((lane >> 3) & 1) * 16;
                ldsm2(kh, st + bo);
                ldsm2(kl, st + KVTILE + bo);
                mma16816(s[nf], qah[kk], kh);
                mma16816(s[nf], qah[kk], kl);
                mma16816(s[nf], qal[kk], kh);
            }
        }

        // ---- scale + mask ----
        const bool diagc = (c >= 2 * qt);
#pragma unroll
        for (int nf = 0; nf < 8; nf++) {
#pragma unroll
            for (int j = 0; j < 4; j++) {
                float v = s[nf][j] * 0.125f;
                if (diagc) {
                    const int col = c * ST + nf * 8 + 2 * (lane & 3) + (j & 1);
                    const int row = rowa + ((j >> 1) << 3);
                    if (col > row) v = -1e30f;
                }
                s[nf][j] = v;
            }
        }

        // ---- online softmax (warp-local, quad shuffles) ----
        float rma = -1e30f, rmb = -1e30f;
#pragma unroll
        for (int nf = 0; nf < 8; nf++) {
            rma = fmaxf(rma, fmaxf(s[nf][0], s[nf][1]));
            rmb = fmaxf(rmb, fmaxf(s[nf][2], s[nf][3]));
        }
        rma = fmaxf(rma, __shfl_xor_sync(0xffffffffu, rma, 1));
        rma = fmaxf(rma, __shfl_xor_sync(0xffffffffu, rma, 2));
        rmb = fmaxf(rmb, __shfl_xor_sync(0xffffffffu, rmb, 1));
        rmb = fmaxf(rmb, __shfl_xor_sync(0xffffffffu, rmb, 2));

        const float mna = fmaxf(m_[0], rma);
        const float mnb = fmaxf(m_[1], rmb);
        const float ca = __expf(m_[0] - mna);
        const float cb = __expf(m_[1] - mnb);
        float sa = 0.0f, sbv = 0.0f;
#pragma unroll
        for (int nf = 0; nf < 8; nf++) {
            s[nf][0] = __expf(s[nf][0] - mna);
            s[nf][1] = __expf(s[nf][1] - mna);
            s[nf][2] = __expf(s[nf][2] - mnb);
            s[nf][3] = __expf(s[nf][3] - mnb);
            sa += s[nf][0] + s[nf][1];
            sbv += s[nf][2] + s[nf][3];
        }
        sa += __shfl_xor_sync(0xffffffffu, sa, 1);
        sa += __shfl_xor_sync(0xffffffffu, sa, 2);
        sbv += __shfl_xor_sync(0xffffffffu, sbv, 1);
        sbv += __shfl_xor_sync(0xffffffffu, sbv, 2);
        l_[0] = l_[0] * ca + sa;
        l_[1] = l_[1] * cb + sbv;
        m_[0] = mna;
        m_[1] = mnb;
#pragma unroll
        for (int nf = 0; nf < 8; nf++) {
            o[nf][0] *= ca;
            o[nf][1] *= ca;
            o[nf][2] *= cb;
            o[nf][3] *= cb;
        }

        // ---- O += P V (P split in registers, V via ldmatrix.trans) ----
#pragma unroll
        for (int kk = 0; kk < 4; kk++) {
            uint32_t pah[4], pal[4];
            split2(s[2 * kk][0], s[2 * kk][1], pah[0], pal[0]);
            split2(s[2 * kk][2], s[2 * kk][3], pah[1], pal[1]);
            split2(s[2 * kk + 1][0], s[2 * kk + 1][1], pah[2], pal[2]);
            split2(s[2 * kk + 1][2], s[2 * kk + 1][3], pah[3], pal[3]);
#pragma unroll
            for (int nf = 0; nf < 8; nf++) {
                uint32_t vh[2], vl[2];
                const uint32_t vo = (kk * 16 + (lane & 15)) * KROWB + nf * 16;
                ldsm2t(vh, st + 2 * KVTILE + vo);
                ldsm2t(vl, st + 3 * KVTILE + vo);
                mma16816(o[nf], pah, vh);
                mma16816(o[nf], pah, vl);
                mma16816(o[nf], pal, vh);
            }
        }
        __syncthreads();  // all warps done with stage before overwrite
        if (c + 2 < nch) load_kv(c + 2, c & 1);
    }

    // ---- epilogue: normalize, split to bf16 hi/lo, write [b*s, e] ----
    const int b = bh >> 4;
    const int h = bh & 15;
    const float ia = 1.0f / l_[0];
    const float ib = 1.0f / l_[1];
#pragma unroll
    for (int nf = 0; nf < 8; nf++) {
        const int e = h * 64 + nf * 8 + 2 * (lane & 3);
        uint32_t hv, lv;
        split2(o[nf][0] * ia, o[nf][1] * ia, hv, lv);
        size_t idx = (size_t)(b * SEQL + rowa) * EMB + e;
        *(uint32_t*)&Ohi[idx] = hv;
        *(uint32_t*)&Olo[idx] = lv;
        split2(o[nf][2] * ib, o[nf][3] * ib, hv, lv);
        idx = (size_t)(b * SEQL + rowa + 8) * EMB + e;
        *(uint32_t*)&Ohi[idx] = hv;
        *(uint32_t*)&Olo[idx] = lv;
    }
}

// ---------------- launch -----------------------------------------------------
extern "C" void kernel_launch(void* const* d_in, const int* in_sizes, int n_in,
                              void* d_out, int out_size) {
    const float* x = (const float*)d_in[0];
    const float* w_q = (const float*)d_in[1];
    const float* w_k = (const float*)d_in[2];
    const float* w_v = (const float*)d_in[3];
    const float* w_o = (const float*)d_in[4];
    float* out = (float*)d_out;

    __nv_bfloat16 *xhi, *xlo, *ahi, *alo;
    __nv_bfloat16 *qhi, *qlo, *khi, *klo, *vhi, *vlo;
    __nv_bfloat16 *wqh, *wql, *wkh, *wkl, *wvh, *wvl, *woh, *wol;
    cudaGetSymbolAddress((void**)&xhi, g_xhi);
    cudaGetSymbolAddress((void**)&xlo, g_xlo);
    cudaGetSymbolAddress((void**)&ahi, g_ahi);
    cudaGetSymbolAddress((void**)&alo, g_alo);
    cudaGetSymbolAddress((void**)&qhi, g_qhi);
    cudaGetSymbolAddress((void**)&qlo, g_qlo);
    cudaGetSymbolAddress((void**)&khi, g_khi);
    cudaGetSymbolAddress((void**)&klo, g_klo);
    cudaGetSymbolAddress((void**)&vhi, g_vhi);
    cudaGetSymbolAddress((void**)&vlo, g_vlo);
    cudaGetSymbolAddress((void**)&wqh, g_wqhi);
    cudaGetSymbolAddress((void**)&wql, g_wqlo);
    cudaGetSymbolAddress((void**)&wkh, g_wkhi);
    cudaGetSymbolAddress((void**)&wkl, g_wklo);
    cudaGetSymbolAddress((void**)&wvh, g_wvhi);
    cudaGetSymbolAddress((void**)&wvl, g_wvlo);
    cudaGetSymbolAddress((void**)&woh, g_wohi);
    cudaGetSymbolAddress((void**)&wol, g_wolo);

    cudaFuncSetAttribute(gemm_mma<0>, cudaFuncAttributeMaxDynamicSharedMemorySize, SM_TOTAL);
    cudaFuncSetAttribute(gemm_mma<1>, cudaFuncAttributeMaxDynamicSharedMemorySize, SM_TOTAL);
    cudaFuncSetAttribute(attn_mma, cudaFuncAttributeMaxDynamicSharedMemorySize, AT_SMEM);

    const int nx4 = MROWS * EMB / 4;
    const int nw4 = EMB * EMB / 4;
    cvt_split<<<nx4 / 256, 256>>>(x, xhi, xlo, nx4);
    cvt_split<<<nw4 / 256, 256>>>(w_q, wqh, wql, nw4);
    cvt_split<<<nw4 / 256, 256>>>(w_k, wkh, wkl, nw4);
    cvt_split<<<nw4 / 256, 256>>>(w_v, wvh, wvl, nw4);
    cvt_split<<<nw4 / 256, 256>>>(w_o, woh, wol, nw4);

    dim3 ggrid(EMB / TN, MROWS / TM);  // (8, 32)
    gemm_mma<1><<<ggrid, 256, SM_TOTAL>>>(xhi, xlo, wqh, wql, nullptr, qhi, qlo);
    gemm_mma<1><<<ggrid, 256, SM_TOTAL>>>(xhi, xlo, wkh, wkl, nullptr, khi, klo);
    gemm_mma<1><<<ggrid, 256, SM_TOTAL>>>(xhi, xlo, wvh, wvl, nullptr, vhi, vlo);

    attn_mma<<<(SEQL / QT) * BSZ * NH, 256, AT_SMEM>>>(qhi, qlo, khi, klo, vhi, vlo,
                                                       ahi, alo);

    gemm_mma<0><<<ggrid, 256, SM_TOTAL>>>(ahi, alo, woh, wol, out, nullptr, nullptr);
}